// round 5
// baseline (speedup 1.0000x reference)
#include <cuda_runtime.h>

#define D_IN     3072
#define H1       32
#define OUT_N    10
#define R_TILE   64            // rows per block
#define KC       64            // K chunk
#define KP       68            // padded smem row stride (floats)
#define NTHREADS 128
#define N_ROWS   32768
#define NKB      (D_IN / KC)   // 48 chunks

#define XSZ (R_TILE * KP)      // 4352 floats per x buffer
#define WSZ (H1 * KP)          // 2176 floats per w buffer

__device__ float g_Scol[H1];   // column sums of w1 (per output j)

// ---------------------------------------------------------------------------
// cp.async helpers
// ---------------------------------------------------------------------------
__device__ __forceinline__ void cp16(void* smem_dst, const void* gsrc) {
    unsigned s = (unsigned)__cvta_generic_to_shared(smem_dst);
    asm volatile("cp.async.cg.shared.global [%0], [%1], 16;\n" :: "r"(s), "l"(gsrc));
}
__device__ __forceinline__ void cp_commit() {
    asm volatile("cp.async.commit_group;\n" ::: "memory");
}
template<int N>
__device__ __forceinline__ void cp_wait() {
    asm volatile("cp.async.wait_group %0;\n" :: "n"(N) : "memory");
}

// ---------------------------------------------------------------------------
// Kernel 1: S_j = sum_k w1[j,k]   (32 blocks, one per output j)
// ---------------------------------------------------------------------------
__global__ void colsum_kernel(const float* __restrict__ w1) {
    __shared__ float red[4];
    int j    = blockIdx.x;
    int tid  = threadIdx.x;
    int lane = tid & 31;
    int wrp  = tid >> 5;
    const float* row = w1 + (size_t)j * D_IN;
    float s = 0.f;
    for (int k = tid; k < D_IN; k += 128) s += row[k];
    #pragma unroll
    for (int m = 16; m; m >>= 1) s += __shfl_xor_sync(0xffffffffu, s, m);
    if (lane == 0) red[wrp] = s;
    __syncthreads();
    if (tid == 0) g_Scol[j] = red[0] + red[1] + red[2] + red[3];
}

// ---------------------------------------------------------------------------
// Kernel 2: fused stats + (x @ w1^T) + norm-correction + L1/L2/L3 + LeakyReLU
//           double-buffered cp.async pipeline
// ---------------------------------------------------------------------------
__global__ __launch_bounds__(NTHREADS) void fused_kernel(
    const float* __restrict__ x,  const float* __restrict__ w1,
    const float* __restrict__ b1, const float* __restrict__ w2,
    const float* __restrict__ b2, const float* __restrict__ w3,
    const float* __restrict__ b3, float* __restrict__ out)
{
    extern __shared__ float sm[];
    float* xs   = sm;                       // 2 * XSZ
    float* ws   = xs + 2 * XSZ;             // 2 * WSZ
    float* sumS = ws + 2 * WSZ;             // 64
    float* sqS  = sumS + R_TILE;            // 64
    float* w2S  = sqS + R_TILE;             // 32*33
    float* w3S  = w2S + H1 * 33;            // 32*33 (zero padded)
    float* b1S  = w3S + H1 * 33;            // 32
    float* b2S  = b1S + H1;                 // 32
    float* b3S  = b2S + H1;                 // 32 (zero padded)
    float* ScS  = b3S + H1;                 // 32

    const int tid     = threadIdx.x;
    const int rowbase = blockIdx.x * R_TILE;
    const int wrp     = tid >> 5;
    const int lane    = tid & 31;
    const int sub     = lane & 7;
    const int rloc    = lane >> 3;

    // ---- kick off chunk 0 loads immediately ----
    {
        const int k0 = 0;
        #pragma unroll
        for (int i = 0; i < 8; i++) {
            int idx = tid + NTHREADS * i;         // 0..1023
            int r   = idx >> 4;
            int k4  = idx & 15;
            cp16(xs + r * KP + k4 * 4,
                 x + (size_t)(rowbase + r) * D_IN + k0 + k4 * 4);
        }
        #pragma unroll
        for (int i = 0; i < 4; i++) {
            int idx = tid + NTHREADS * i;         // 0..511
            int c   = idx >> 4;
            int k4  = idx & 15;
            cp16(ws + c * KP + k4 * 4,
                 w1 + (size_t)c * D_IN + k0 + k4 * 4);
        }
        cp_commit();
    }

    // ---- init small smem (overlaps with chunk-0 cp.async) ----
    for (int i = tid; i < H1 * 33; i += NTHREADS) w3S[i] = 0.f;
    for (int i = tid; i < H1 * H1; i += NTHREADS)
        w2S[(i >> 5) * 33 + (i & 31)] = w2[i];
    if (tid < R_TILE) { sumS[tid] = 0.f; sqS[tid] = 0.f; }
    if (tid < H1) {
        b1S[tid] = b1[tid];
        b2S[tid] = b2[tid];
        b3S[tid] = (tid < OUT_N) ? b3[tid] : 0.f;
        ScS[tid] = g_Scol[tid];
    }
    __syncthreads();   // w3S zeros visible
    for (int i = tid; i < OUT_N * H1; i += NTHREADS)
        w3S[(i >> 5) * 33 + (i & 31)] = w3[i];

    // ---- register tile: 4 rows x 4 cols ----
    const int rg = tid >> 3;     // 0..15 -> rows rg*4 .. rg*4+3
    const int cg = tid & 7;      // 0..7  -> cols cg*4 .. cg*4+3
    float acc[4][4];
    #pragma unroll
    for (int i = 0; i < 4; i++)
        #pragma unroll
        for (int j = 0; j < 4; j++) acc[i][j] = 0.f;

    for (int kb = 0; kb < NKB; kb++) {
        const int cur = kb & 1;

        // issue next chunk's loads into the other buffer
        if (kb + 1 < NKB) {
            const int k0 = (kb + 1) * KC;
            float* xb = xs + (cur ^ 1) * XSZ;
            float* wb = ws + (cur ^ 1) * WSZ;
            #pragma unroll
            for (int i = 0; i < 8; i++) {
                int idx = tid + NTHREADS * i;
                int r   = idx >> 4;
                int k4  = idx & 15;
                cp16(xb + r * KP + k4 * 4,
                     x + (size_t)(rowbase + r) * D_IN + k0 + k4 * 4);
            }
            #pragma unroll
            for (int i = 0; i < 4; i++) {
                int idx = tid + NTHREADS * i;
                int c   = idx >> 4;
                int k4  = idx & 15;
                cp16(wb + c * KP + k4 * 4,
                     w1 + (size_t)c * D_IN + k0 + k4 * 4);
            }
            cp_commit();
            cp_wait<1>();        // current chunk's group done; next in flight
        } else {
            cp_wait<0>();
        }
        __syncthreads();

        const float* xcur = xs + cur * XSZ;
        const float* wcur = ws + cur * WSZ;

        // ---- per-row stats (sum, sumsq) from staged tile ----
        #pragma unroll
        for (int p = 0; p < 4; p++) {
            int row = wrp * 16 + p * 4 + rloc;
            const float* xr = xcur + row * KP + sub * 8;
            float4 a = *(const float4*)(xr);
            float4 b = *(const float4*)(xr + 4);
            float s = ((a.x + a.y) + (a.z + a.w)) + ((b.x + b.y) + (b.z + b.w));
            float q = a.x * a.x;
            q = fmaf(a.y, a.y, q); q = fmaf(a.z, a.z, q); q = fmaf(a.w, a.w, q);
            q = fmaf(b.x, b.x, q); q = fmaf(b.y, b.y, q);
            q = fmaf(b.z, b.z, q); q = fmaf(b.w, b.w, q);
            #pragma unroll
            for (int m = 1; m < 8; m <<= 1) {
                s += __shfl_xor_sync(0xffffffffu, s, m);
                q += __shfl_xor_sync(0xffffffffu, q, m);
            }
            if (sub == 0) { sumS[row] += s; sqS[row] += q; }
        }

        // ---- main FMA loop ----
        const float* xbase = xcur + rg * 4 * KP;
        const float* wbase = wcur + cg * 4 * KP;
        #pragma unroll
        for (int k4 = 0; k4 < KC / 4; k4++) {
            float4 wv[4];
            #pragma unroll
            for (int j = 0; j < 4; j++)
                wv[j] = *(const float4*)(wbase + j * KP + k4 * 4);
            #pragma unroll
            for (int i = 0; i < 4; i++) {
                float4 xv = *(const float4*)(xbase + i * KP + k4 * 4);
                #pragma unroll
                for (int j = 0; j < 4; j++) {
                    acc[i][j] = fmaf(xv.x, wv[j].x, acc[i][j]);
                    acc[i][j] = fmaf(xv.y, wv[j].y, acc[i][j]);
                    acc[i][j] = fmaf(xv.z, wv[j].z, acc[i][j]);
                    acc[i][j] = fmaf(xv.w, wv[j].w, acc[i][j]);
                }
            }
        }
        __syncthreads();         // buffer free before it is reloaded
    }

    // ---- stage dots to smem (reuse xs buffer 0), stride 33 ----
    float* dotS = xs;
    #pragma unroll
    for (int i = 0; i < 4; i++)
        #pragma unroll
        for (int j = 0; j < 4; j++)
            dotS[(rg * 4 + i) * 33 + (cg * 4 + j)] = acc[i][j];
    __syncthreads();

    // ---- epilogue: per-row normalization correction + L1/L2/L3 ----
    const int j = lane;                 // output index 0..31
    const float invD  = 1.0f / (float)D_IN;
    const float invDm = 1.0f / (float)(D_IN - 1);
    for (int p = 0; p < 16; p++) {
        int row = wrp * 16 + p;
        float mean = sumS[row] * invD;
        float var  = (sqS[row] - (float)D_IN * mean * mean) * invDm;
        float rstd = rsqrtf(var);
        float d    = dotS[row * 33 + j];
        float y    = fmaf(d - mean * ScS[j], rstd, b1S[j]);
        y = fmaxf(y, 0.01f * y);                       // LeakyReLU
        float a2 = b2S[j];
        #pragma unroll
        for (int i = 0; i < H1; i++) {
            float hi = __shfl_sync(0xffffffffu, y, i);
            a2 = fmaf(w2S[j * 33 + i], hi, a2);
        }
        a2 = fmaxf(a2, 0.01f * a2);
        float a3 = b3S[j];
        #pragma unroll
        for (int i = 0; i < H1; i++) {
            float hi = __shfl_sync(0xffffffffu, a2, i);
            a3 = fmaf(w3S[j * 33 + i], hi, a3);
        }
        a3 = fmaxf(a3, 0.01f * a3);
        if (j < OUT_N)
            out[(size_t)(rowbase + row) * OUT_N + j] = a3;
    }
}

// ---------------------------------------------------------------------------
extern "C" void kernel_launch(void* const* d_in, const int* in_sizes, int n_in,
                              void* d_out, int out_size) {
    const float* x  = (const float*)d_in[0];
    const float* w1 = (const float*)d_in[1];
    const float* b1 = (const float*)d_in[2];
    const float* w2 = (const float*)d_in[3];
    const float* b2 = (const float*)d_in[4];
    const float* w3 = (const float*)d_in[5];
    const float* b3 = (const float*)d_in[6];
    float* out = (float*)d_out;

    static bool attr_set = false;
    const int smem_bytes =
        (2 * XSZ + 2 * WSZ + 2 * R_TILE + 2 * H1 * 33 + 4 * H1) * 4;
    if (!attr_set) {
        cudaFuncSetAttribute(fused_kernel,
                             cudaFuncAttributeMaxDynamicSharedMemorySize, smem_bytes);
        attr_set = true;
    }

    colsum_kernel<<<H1, 128>>>(w1);
    fused_kernel<<<N_ROWS / R_TILE, NTHREADS, smem_bytes>>>(x, w1, b1, w2, b2, w3, b3, out);
}

// round 7
// speedup vs baseline: 1.5954x; 1.5954x over previous
#include <cuda_runtime.h>

#define D_IN     3072
#define H1       32
#define OUT_N    10
#define R_TILE   64            // rows per block
#define KC       32            // K chunk
#define KP       36            // padded smem row stride (floats); +4 pad per 8 rows
#define NTHREADS 64
#define N_ROWS   32768
#define NKB      (D_IN / KC)   // 96 chunks

#define XBUF (R_TILE * KP + (R_TILE / 8) * 4)   // 2336 floats per x buffer
#define WSZ  (H1 * KP)                          // 1152 floats per w buffer

__device__ float g_Scol[H1];   // column sums of w1

// ---------------------------------------------------------------------------
// packed f32x2 helpers (FFMA2 — PTX-only on sm_103a)
// ---------------------------------------------------------------------------
__device__ __forceinline__ void fma2(unsigned long long& d,
                                     unsigned long long a, unsigned long long b) {
    asm("fma.rn.f32x2 %0, %1, %2, %0;" : "+l"(d) : "l"(a), "l"(b));
}
__device__ __forceinline__ void add2(unsigned long long& d, unsigned long long a) {
    asm("add.rn.f32x2 %0, %1, %0;" : "+l"(d) : "l"(a));
}
__device__ __forceinline__ float lohi(unsigned long long v) {
    union { unsigned long long u; float2 f; } t; t.u = v;
    return t.f.x + t.f.y;
}

// ---------------------------------------------------------------------------
// cp.async helpers
// ---------------------------------------------------------------------------
__device__ __forceinline__ void cp16(void* smem_dst, const void* gsrc) {
    unsigned s = (unsigned)__cvta_generic_to_shared(smem_dst);
    asm volatile("cp.async.cg.shared.global [%0], [%1], 16;\n" :: "r"(s), "l"(gsrc));
}
__device__ __forceinline__ void cp_commit() {
    asm volatile("cp.async.commit_group;\n" ::: "memory");
}
template<int N>
__device__ __forceinline__ void cp_wait() {
    asm volatile("cp.async.wait_group %0;\n" :: "n"(N) : "memory");
}

// x smem row offset: +4-word pad every 8 rows (breaks 128B bank aliasing of
// the stride-8 row groups used by the stats load)
__device__ __forceinline__ int xrow(int r) { return r * KP + (r >> 3) * 4; }

// ---------------------------------------------------------------------------
// Kernel 1: S_j = sum_k w1[j,k]
// ---------------------------------------------------------------------------
__global__ void colsum_kernel(const float* __restrict__ w1) {
    __shared__ float red[4];
    int j = blockIdx.x, tid = threadIdx.x, lane = tid & 31, wrp = tid >> 5;
    const float* row = w1 + (size_t)j * D_IN;
    float s = 0.f;
    for (int k = tid; k < D_IN; k += 128) s += row[k];
    #pragma unroll
    for (int m = 16; m; m >>= 1) s += __shfl_xor_sync(0xffffffffu, s, m);
    if (lane == 0) red[wrp] = s;
    __syncthreads();
    if (tid == 0) g_Scol[j] = red[0] + red[1] + red[2] + red[3];
}

// ---------------------------------------------------------------------------
// Kernel 2: fused stats + GEMM (f32x2) + norm + L1/L2/L3 + LeakyReLU
// ---------------------------------------------------------------------------
__global__ __launch_bounds__(NTHREADS) void fused_kernel(
    const float* __restrict__ x,  const float* __restrict__ w1,
    const float* __restrict__ b1, const float* __restrict__ w2,
    const float* __restrict__ b2, const float* __restrict__ w3,
    const float* __restrict__ b3, float* __restrict__ out)
{
    extern __shared__ float sm[];
    float* xs   = sm;                      // 2 * XBUF
    float* ws   = xs + 2 * XBUF;           // 2 * WSZ
    float* sumS = ws + 2 * WSZ;            // 64
    float* sqS  = sumS + R_TILE;           // 64
    float* w2S  = sqS + R_TILE;            // 32*33
    float* w3S  = w2S + H1 * 33;           // 32*33 (zero padded)
    float* b1S  = w3S + H1 * 33;           // 32
    float* b2S  = b1S + H1;                // 32
    float* b3S  = b2S + H1;                // 32 (zero padded)
    float* ScS  = b3S + H1;                // 32

    const int tid     = threadIdx.x;
    const int rowbase = blockIdx.x * R_TILE;
    const int rg      = tid >> 3;          // 0..7 : owns rows rg + 8i
    const int cg      = tid & 7;           // 0..7 : owns cols cg + 8j

    // ---- kick off chunk 0 cp.async ----
    {
        #pragma unroll
        for (int i = 0; i < 8; i++) {                 // x: 512 float4
            int idx = tid + NTHREADS * i;
            int r   = idx >> 3;
            int k4  = idx & 7;
            cp16(xs + xrow(r) + k4 * 4,
                 x + (size_t)(rowbase + r) * D_IN + k4 * 4);
        }
        #pragma unroll
        for (int i = 0; i < 4; i++) {                 // w: 256 float4
            int idx = tid + NTHREADS * i;
            int c   = idx >> 3;
            int k4  = idx & 7;
            cp16(ws + c * KP + k4 * 4,
                 w1 + (size_t)c * D_IN + k4 * 4);
        }
        cp_commit();
    }

    // ---- small smem init (overlaps chunk-0 loads) ----
    for (int i = tid; i < H1 * 33; i += NTHREADS) w3S[i] = 0.f;
    for (int i = tid; i < H1 * H1; i += NTHREADS)
        w2S[(i >> 5) * 33 + (i & 31)] = w2[i];
    if (tid < H1) {
        b1S[tid] = b1[tid];
        b2S[tid] = b2[tid];
        b3S[tid] = (tid < OUT_N) ? b3[tid] : 0.f;
        ScS[tid] = g_Scol[tid];
    }
    __syncthreads();    // w3S zeros visible
    for (int i = tid; i < OUT_N * H1; i += NTHREADS)
        w3S[(i >> 5) * 33 + (i & 31)] = w3[i];

    // ---- accumulators (packed even/odd-k partial sums) ----
    unsigned long long acc[8][4];
    #pragma unroll
    for (int i = 0; i < 8; i++)
        #pragma unroll
        for (int j = 0; j < 4; j++) acc[i][j] = 0ull;
    unsigned long long sum2 = 0ull, sq2 = 0ull;   // stats of row rg + 8*cg

    for (int kb = 0; kb < NKB; kb++) {
        const int cur = kb & 1;

        if (kb + 1 < NKB) {                    // prefetch next chunk
            const int k0 = (kb + 1) * KC;
            float* xb = xs + (cur ^ 1) * XBUF;
            float* wb = ws + (cur ^ 1) * WSZ;
            #pragma unroll
            for (int i = 0; i < 8; i++) {
                int idx = tid + NTHREADS * i;
                int r   = idx >> 3;
                int k4  = idx & 7;
                cp16(xb + xrow(r) + k4 * 4,
                     x + (size_t)(rowbase + r) * D_IN + k0 + k4 * 4);
            }
            #pragma unroll
            for (int i = 0; i < 4; i++) {
                int idx = tid + NTHREADS * i;
                int c   = idx >> 3;
                int k4  = idx & 7;
                cp16(wb + c * KP + k4 * 4,
                     w1 + (size_t)c * D_IN + k0 + k4 * 4);
            }
            cp_commit();
            cp_wait<1>();
        } else {
            cp_wait<0>();
        }
        __syncthreads();

        const float* xb = xs + cur * XBUF + rg * KP;   // row rg+8i at +i*292
        const float* wb = ws + cur * WSZ + cg * KP;    // col cg+8j at +j*288

        #pragma unroll
        for (int k4 = 0; k4 < KC / 4; k4++) {
            ulonglong2 wv[4];
            #pragma unroll
            for (int j = 0; j < 4; j++)
                wv[j] = *(const ulonglong2*)(wb + j * (8 * KP) + k4 * 4);

            // register stats for this thread's dedicated row (rg + 8*cg)
            {
                ulonglong2 sv = *(const ulonglong2*)(xb + cg * (8 * KP + 4) + k4 * 4);
                add2(sum2, sv.x); add2(sum2, sv.y);
                fma2(sq2, sv.x, sv.x); fma2(sq2, sv.y, sv.y);
            }

            #pragma unroll
            for (int i = 0; i < 8; i++) {
                ulonglong2 xv = *(const ulonglong2*)(xb + i * (8 * KP + 4) + k4 * 4);
                #pragma unroll
                for (int j = 0; j < 4; j++) fma2(acc[i][j], xv.x, wv[j].x);
                #pragma unroll
                for (int j = 0; j < 4; j++) fma2(acc[i][j], xv.y, wv[j].y);
            }
        }
        __syncthreads();      // buffer reusable
    }

    // ---- stats + dots to smem ----
    sumS[rg + 8 * cg] = lohi(sum2);
    sqS [rg + 8 * cg] = lohi(sq2);
    float* dotS = xs;                        // reuse x buffer 0 (free now)
    #pragma unroll
    for (int i = 0; i < 8; i++)
        #pragma unroll
        for (int j = 0; j < 4; j++)
            dotS[(rg + 8 * i) * 33 + (cg + 8 * j)] = lohi(acc[i][j]);
    __syncthreads();

    // ---- epilogue: normalization correction + L2/L3 via shuffles ----
    const int wrp  = tid >> 5;
    const int j    = tid & 31;
    const float invD  = 1.0f / (float)D_IN;
    const float invDm = 1.0f / (float)(D_IN - 1);
    for (int p = 0; p < 32; p++) {
        int row = wrp * 32 + p;
        float mean = sumS[row] * invD;
        float var  = (sqS[row] - (float)D_IN * mean * mean) * invDm;
        float rstd = rsqrtf(var);
        float d    = dotS[row * 33 + j];
        float y    = fmaf(d - mean * ScS[j], rstd, b1S[j]);
        y = fmaxf(y, 0.01f * y);
        float a2 = b2S[j];
        #pragma unroll
        for (int i = 0; i < H1; i++) {
            float hi = __shfl_sync(0xffffffffu, y, i);
            a2 = fmaf(w2S[j * 33 + i], hi, a2);
        }
        a2 = fmaxf(a2, 0.01f * a2);
        float a3 = b3S[j];
        #pragma unroll
        for (int i = 0; i < H1; i++) {
            float hi = __shfl_sync(0xffffffffu, a2, i);
            a3 = fmaf(w3S[j * 33 + i], hi, a3);
        }
        a3 = fmaxf(a3, 0.01f * a3);
        if (j < OUT_N)
            out[(size_t)(rowbase + row) * OUT_N + j] = a3;
    }
}

// ---------------------------------------------------------------------------
extern "C" void kernel_launch(void* const* d_in, const int* in_sizes, int n_in,
                              void* d_out, int out_size) {
    const float* x  = (const float*)d_in[0];
    const float* w1 = (const float*)d_in[1];
    const float* b1 = (const float*)d_in[2];
    const float* w2 = (const float*)d_in[3];
    const float* b2 = (const float*)d_in[4];
    const float* w3 = (const float*)d_in[5];
    const float* b3 = (const float*)d_in[6];
    float* out = (float*)d_out;

    static bool attr_set = false;
    const int smem_bytes =
        (2 * XBUF + 2 * WSZ + 2 * R_TILE + 2 * H1 * 33 + 4 * H1) * 4;
    if (!attr_set) {
        cudaFuncSetAttribute(fused_kernel,
                             cudaFuncAttributeMaxDynamicSharedMemorySize, smem_bytes);
        attr_set = true;
    }

    colsum_kernel<<<H1, 128>>>(w1);
    fused_kernel<<<N_ROWS / R_TILE, NTHREADS, smem_bytes>>>(x, w1, b1, w2, b2, w3, b3, out);
}

// round 11
// speedup vs baseline: 4.7773x; 2.9944x over previous
#include <cuda_runtime.h>
#include <cuda_bf16.h>
#include <cstdint>

#define D_IN    3072
#define H1      32
#define OUT_N   10
#define M_TILE  128
#define KC      64              // fp32 K per chunk
#define NKB     (D_IN / KC)    // 48
#define NT      256
#define N_ROWS  32768

// byte offsets from 1024-aligned smem base
#define SM_A      0             // 2 x 32768  (A bf16: 128 rows x [hi 128B | lo 128B])
#define SM_B      65536         // 2 x 8192   (B bf16:  32 rows x [hi | lo])
#define SM_SUM    81920         // 128 f
#define SM_SQ     82432         // 128 f
#define SM_W2     82944         // 32*32 f
#define SM_W3     87040         // 10*32 f
#define SM_B1     88320
#define SM_B2     88448
#define SM_B3     88576
#define SM_SC     88704
#define SM_BYTES  (88832 + 1024)

#define SWZ(o) ((o) ^ (((o) >> 3) & 0x70))

__device__ float g_Scol[H1];

// ---------------------------------------------------------------------------
// helpers
// ---------------------------------------------------------------------------
__device__ __forceinline__ uint32_t smem_u32(const void* p) {
    uint32_t a;
    asm("{ .reg .u64 t; cvta.to.shared.u64 t, %1; cvt.u32.u64 %0, t; }"
        : "=r"(a) : "l"(p));
    return a;
}
__device__ __forceinline__ unsigned long long pk(float a, float b) {
    unsigned long long r;
    asm("mov.b64 %0, {%1, %2};" : "=l"(r) : "f"(a), "f"(b));
    return r;
}
__device__ __forceinline__ void add2(unsigned long long& d, unsigned long long a) {
    asm("add.rn.f32x2 %0, %1, %0;" : "+l"(d) : "l"(a));
}
__device__ __forceinline__ void fma2(unsigned long long& d,
                                     unsigned long long a, unsigned long long b) {
    asm("fma.rn.f32x2 %0, %1, %2, %0;" : "+l"(d) : "l"(a), "l"(b));
}
__device__ __forceinline__ float lohi(unsigned long long v) {
    union { unsigned long long u; float2 f; } t; t.u = v;
    return t.f.x + t.f.y;
}
__device__ __forceinline__ void sts128(uint32_t addr, const uint32_t* r) {
    asm volatile("st.shared.v4.b32 [%0], {%1,%2,%3,%4};"
                 :: "r"(addr), "r"(r[0]), "r"(r[1]), "r"(r[2]), "r"(r[3]) : "memory");
}
// 8 consecutive fp32 -> 4 u32 bf16-hi pairs + 4 u32 bf16-lo pairs (k order kept)
__device__ __forceinline__ void cvt8(float4 a, float4 b, uint32_t* h, uint32_t* l) {
    float v[8] = {a.x, a.y, a.z, a.w, b.x, b.y, b.z, b.w};
    #pragma unroll
    for (int k = 0; k < 4; k++) {
        float v0 = v[2 * k], v1 = v[2 * k + 1];
        uint32_t hw;
        asm("cvt.rn.bf16x2.f32 %0, %1, %2;" : "=r"(hw) : "f"(v1), "f"(v0)); // lo = v0
        float h0 = __uint_as_float(hw << 16);
        float h1 = __uint_as_float(hw & 0xffff0000u);
        float l0 = v0 - h0, l1 = v1 - h1;
        uint32_t lw;
        asm("cvt.rn.bf16x2.f32 %0, %1, %2;" : "=r"(lw) : "f"(l1), "f"(l0));
        h[k] = hw; l[k] = lw;
    }
}
__device__ __forceinline__ void ldm4(uint32_t* r, uint32_t addr) {
    asm volatile("ldmatrix.sync.aligned.m8n8.x4.shared.b16 {%0,%1,%2,%3}, [%4];"
                 : "=r"(r[0]), "=r"(r[1]), "=r"(r[2]), "=r"(r[3]) : "r"(addr));
}
__device__ __forceinline__ void mma_bf16(float* d, const uint32_t* a,
                                         const uint32_t* b) {
    asm volatile(
        "mma.sync.aligned.m16n8k16.row.col.f32.bf16.bf16.f32 "
        "{%0,%1,%2,%3}, {%4,%5,%6,%7}, {%8,%9}, {%0,%1,%2,%3};"
        : "+f"(d[0]), "+f"(d[1]), "+f"(d[2]), "+f"(d[3])
        : "r"(a[0]), "r"(a[1]), "r"(a[2]), "r"(a[3]), "r"(b[0]), "r"(b[1]));
}

// ---------------------------------------------------------------------------
// Kernel 1: S_j = sum_k w1[j,k]
// ---------------------------------------------------------------------------
__global__ void colsum_kernel(const float* __restrict__ w1) {
    __shared__ float red[4];
    int j = blockIdx.x, tid = threadIdx.x, lane = tid & 31, wrp = tid >> 5;
    const float* row = w1 + (size_t)j * D_IN;
    float s = 0.f;
    for (int k = tid; k < D_IN; k += 128) s += row[k];
    #pragma unroll
    for (int m = 16; m; m >>= 1) s += __shfl_xor_sync(0xffffffffu, s, m);
    if (lane == 0) red[wrp] = s;
    __syncthreads();
    if (tid == 0) g_Scol[j] = red[0] + red[1] + red[2] + red[3];
}

// ---------------------------------------------------------------------------
// Kernel 2: fused stats + bf16-split HMMA GEMM + norm + L1/L2/L3
// ---------------------------------------------------------------------------
__global__ __launch_bounds__(NT) void fused_kernel(
    const float* __restrict__ x,  const float* __restrict__ w1,
    const float* __restrict__ b1, const float* __restrict__ w2,
    const float* __restrict__ b2, const float* __restrict__ w3,
    const float* __restrict__ b3, float* __restrict__ out)
{
    extern __shared__ char smraw[];
    const uint32_t sb_u = smem_u32(smraw);
    const uint32_t sb   = (sb_u + 1023u) & ~1023u;
    char* smb = smraw + (sb - sb_u);

    float* sumS = (float*)(smb + SM_SUM);
    float* sqS  = (float*)(smb + SM_SQ);
    float* w2S  = (float*)(smb + SM_W2);
    float* w3S  = (float*)(smb + SM_W3);
    float* b1S  = (float*)(smb + SM_B1);
    float* b2S  = (float*)(smb + SM_B2);
    float* b3S  = (float*)(smb + SM_B3);
    float* ScS  = (float*)(smb + SM_SC);

    const int tid  = threadIdx.x;
    const int wid  = tid >> 5;
    const int lane = tid & 31;
    const int seg  = tid & 7;           // 8-fp32 segment within 64-K chunk
    const int rgrp = tid >> 3;          // 0..31
    const size_t rowbase = (size_t)blockIdx.x * M_TILE;

    // small weights to smem
    for (int i = tid; i < H1 * H1; i += NT)    w2S[i] = w2[i];
    for (int i = tid; i < OUT_N * H1; i += NT) w3S[i] = w3[i];
    if (tid < H1) { b1S[tid] = b1[tid]; b2S[tid] = b2[tid]; ScS[tid] = g_Scol[tid]; }
    if (tid < OUT_N) b3S[tid] = b3[tid];

    // stats accumulators (f32x2), one per owned row (rgrp + 32*i)
    unsigned long long s2[4] = {0,0,0,0}, q2[4] = {0,0,0,0};

    // HMMA accumulators: warp owns rows [16*wid, 16*wid+16), 4 n-steps of 8
    float acc[4][4];
    #pragma unroll
    for (int n = 0; n < 4; n++)
        #pragma unroll
        for (int q = 0; q < 4; q++) acc[n][q] = 0.f;

    // ldmatrix address components (constant per thread)
    const uint32_t a_row = (uint32_t)(16 * wid + (lane & 15));
    const uint32_t a_kad = ((lane >> 4) & 1) * 16;
    const uint32_t b_r0  = (uint32_t)((lane & 7) + ((lane >> 4) & 1) * 8);
    const uint32_t b_kad = ((lane >> 3) & 1) * 16;

    // ---- prologue: LDG chunk 0 ----
    float4 xa[4], xb[4], wa, wb;
    {
        #pragma unroll
        for (int i = 0; i < 4; i++) {
            const float* src = x + (rowbase + rgrp + 32 * i) * D_IN + seg * 8;
            xa[i] = *(const float4*)src;
            xb[i] = *(const float4*)(src + 4);
        }
        const float* wsrc = w1 + (size_t)rgrp * D_IN + seg * 8;
        wa = *(const float4*)wsrc;
        wb = *(const float4*)(wsrc + 4);
    }

    for (int kb = 0; kb < NKB; kb++) {
        const int p = kb & 1;
        const uint32_t Ab = sb + SM_A + p * 32768;
        const uint32_t Bb = sb + SM_B + p * 8192;

        // ---- convert + STS + stats (chunk kb, from regs) ----
        #pragma unroll
        for (int i = 0; i < 4; i++) {
            unsigned long long p0 = pk(xa[i].x, xa[i].y), p1 = pk(xa[i].z, xa[i].w);
            unsigned long long p2 = pk(xb[i].x, xb[i].y), p3 = pk(xb[i].z, xb[i].w);
            add2(s2[i], p0); add2(s2[i], p1); add2(s2[i], p2); add2(s2[i], p3);
            fma2(q2[i], p0, p0); fma2(q2[i], p1, p1);
            fma2(q2[i], p2, p2); fma2(q2[i], p3, p3);

            uint32_t h[4], l[4];
            cvt8(xa[i], xb[i], h, l);
            uint32_t off = (uint32_t)(rgrp + 32 * i) * 128 + seg * 16;
            sts128(Ab + SWZ(off), h);
            sts128(Ab + 16384 + SWZ(off), l);
        }
        {
            uint32_t h[4], l[4];
            cvt8(wa, wb, h, l);
            uint32_t off = (uint32_t)rgrp * 128 + seg * 16;
            sts128(Bb + SWZ(off), h);
            sts128(Bb + 4096 + SWZ(off), l);
        }
        __syncthreads();

        // ---- prefetch chunk kb+1 (overlaps MMA below) ----
        if (kb + 1 < NKB) {
            const int k0 = (kb + 1) * KC;
            #pragma unroll
            for (int i = 0; i < 4; i++) {
                const float* src = x + (rowbase + rgrp + 32 * i) * D_IN + k0 + seg * 8;
                xa[i] = *(const float4*)src;
                xb[i] = *(const float4*)(src + 4);
            }
            const float* wsrc = w1 + (size_t)rgrp * D_IN + k0 + seg * 8;
            wa = *(const float4*)wsrc;
            wb = *(const float4*)(wsrc + 4);
        }

        // ---- per-warp HMMA on buffer p ----
        #pragma unroll
        for (int j = 0; j < 4; j++) {                       // k16 steps
            uint32_t ah[4], al[4];
            uint32_t aoff = SWZ(a_row * 128 + (uint32_t)j * 32 + a_kad);
            ldm4(ah, Ab + aoff);
            ldm4(al, Ab + 16384 + aoff);
            uint32_t bh[2][4], bl[2][4];
            #pragma unroll
            for (int nb = 0; nb < 2; nb++) {
                uint32_t boff = SWZ(((uint32_t)nb * 16 + b_r0) * 128
                                    + (uint32_t)j * 32 + b_kad);
                ldm4(bh[nb], Bb + boff);
                ldm4(bl[nb], Bb + 4096 + boff);
            }
            #pragma unroll
            for (int n = 0; n < 4; n++) {
                const uint32_t* bhn = &bh[n >> 1][(n & 1) * 2];
                const uint32_t* bln = &bl[n >> 1][(n & 1) * 2];
                mma_bf16(acc[n], ah, bhn);      // hi . hi
                mma_bf16(acc[n], al, bhn);      // lo . hi
                mma_bf16(acc[n], ah, bln);      // hi . lo
            }
        }
        // no trailing sync needed: next overwrite of buffer p^1 is guarded by
        // the sync above (all warps finished computing p^1 before issuing it)
    }

    // ---- stats: reduce over the 8 segments sharing each row ----
    #pragma unroll
    for (int i = 0; i < 4; i++) {
        float s = lohi(s2[i]), q = lohi(q2[i]);
        #pragma unroll
        for (int m = 1; m < 8; m <<= 1) {
            s += __shfl_xor_sync(0xffffffffu, s, m);
            q += __shfl_xor_sync(0xffffffffu, q, m);
        }
        if (seg == 0) { sumS[rgrp + 32 * i] = s; sqS[rgrp + 32 * i] = q; }
    }

    // ---- stage accumulators to smem (reuse A buffer 0; last read was kb=46,
    //      finished before the kb=47 sync) ----
    float* dotS = (float*)(smb + SM_A);          // 128 x 33 floats
    {
        const int g = lane >> 2, t = lane & 3;
        #pragma unroll
        for (int n = 0; n < 4; n++) {
            int r0 = 16 * wid + g, c = n * 8 + t * 2;
            dotS[r0 * 33 + c]       = acc[n][0];
            dotS[r0 * 33 + c + 1]   = acc[n][1];
            dotS[(r0+8) * 33 + c]   = acc[n][2];
            dotS[(r0+8) * 33 + c+1] = acc[n][3];
        }
    }
    __syncthreads();

    // ---- epilogue: one thread per row ----
    if (tid < M_TILE) {
        const int row = tid;
        const float invD  = 1.0f / (float)D_IN;
        const float invDm = 1.0f / (float)(D_IN - 1);
        float mean = sumS[row] * invD;
        float var  = (sqS[row] - (float)D_IN * mean * mean) * invDm;
        float rstd = rsqrtf(var);

        float y[32];
        #pragma unroll
        for (int j = 0; j < 32; j++) {
            float d = dotS[row * 33 + j];
            float v = fmaf(d - mean * ScS[j], rstd, b1S[j]);
            y[j] = fmaxf(v, 0.01f * v);
        }
        float a2[32];
        #pragma unroll
        for (int j = 0; j < 32; j++) {
            float s = b2S[j];
            #pragma unroll
            for (int i = 0; i < 32; i++) s = fmaf(w2S[j * 32 + i], y[i], s);
            a2[j] = fmaxf(s, 0.01f * s);
        }
        float a3[OUT_N];
        #pragma unroll
        for (int j = 0; j < OUT_N; j++) {
            float s = b3S[j];
            #pragma unroll
            for (int i = 0; i < 32; i++) s = fmaf(w3S[j * 32 + i], a2[i], s);
            a3[j] = fmaxf(s, 0.01f * s);
        }
        float* op = out + (rowbase + row) * OUT_N;
        #pragma unroll
        for (int j = 0; j < OUT_N; j += 2)
            *(float2*)(op + j) = make_float2(a3[j], a3[j + 1]);
    }
}

// ---------------------------------------------------------------------------
extern "C" void kernel_launch(void* const* d_in, const int* in_sizes, int n_in,
                              void* d_out, int out_size) {
    const float* x  = (const float*)d_in[0];
    const float* w1 = (const float*)d_in[1];
    const float* b1 = (const float*)d_in[2];
    const float* w2 = (const float*)d_in[3];
    const float* b2 = (const float*)d_in[4];
    const float* w3 = (const float*)d_in[5];
    const float* b3 = (const float*)d_in[6];
    float* out = (float*)d_out;

    static bool attr_set = false;
    if (!attr_set) {
        cudaFuncSetAttribute(fused_kernel,
                             cudaFuncAttributeMaxDynamicSharedMemorySize, SM_BYTES);
        attr_set = true;
    }

    colsum_kernel<<<H1, 128>>>(w1);
    fused_kernel<<<N_ROWS / M_TILE, NT, SM_BYTES>>>(x, w1, b1, w2, b2, w3, b3, out);
}